// round 15
// baseline (speedup 1.0000x reference)
#include <cuda_runtime.h>
#include <cuda_fp16.h>
#include <mma.h>
#include <math.h>
#include <stdint.h>

using namespace nvcuda;

// Problem constants
#define SEQ    4096
#define HID    4096
#define NQ     32
#define NKV    8
#define DH     128
#define GRP    4
#define QKV_COLS (NQ*DH + 2*NKV*DH)   // 6144
#define ATT_SCALE 0.08838834764831845f

// Scratch (no cudaMalloc allowed)
__device__ float  g_qkv[(size_t)SEQ * QKV_COLS];      // fp32 qkv (GEMM1 out)
__device__ __half g_qkv_h[(size_t)SEQ * QKV_COLS];    // half q(rope,scaled),k(rope),v
__device__ __half g_attn_h[(size_t)SEQ * (NQ*DH)];    // half attention output
__device__ __half g_hid_h[(size_t)SEQ * HID];
__device__ __half g_wqkv_h[(size_t)HID * QKV_COLS];
__device__ __half g_wo_h[(size_t)(NQ*DH) * HID];

__device__ __forceinline__ void cp_async16(void* smem_dst, const void* gmem_src)
{
    unsigned dst = (unsigned)__cvta_generic_to_shared(smem_dst);
    asm volatile("cp.async.cg.shared.global [%0], [%1], 16;\n" :: "r"(dst), "l"(gmem_src));
}
__device__ __forceinline__ uint32_t h2u(__half2 h) { return *(uint32_t*)&h; }
__device__ __forceinline__ uint32_t s2u(const void* p) {
    return (uint32_t)__cvta_generic_to_shared(p);
}

__device__ __forceinline__ void ldsm_x4(uint32_t* r, uint32_t addr) {
    asm volatile("ldmatrix.sync.aligned.m8n8.x4.shared.b16 {%0,%1,%2,%3}, [%4];"
        : "=r"(r[0]), "=r"(r[1]), "=r"(r[2]), "=r"(r[3]) : "r"(addr));
}
__device__ __forceinline__ void ldsm_x4_t(uint32_t* r, uint32_t addr) {
    asm volatile("ldmatrix.sync.aligned.m8n8.x4.trans.shared.b16 {%0,%1,%2,%3}, [%4];"
        : "=r"(r[0]), "=r"(r[1]), "=r"(r[2]), "=r"(r[3]) : "r"(addr));
}
__device__ __forceinline__ void mma16816(float* d, const uint32_t* a, uint32_t b0, uint32_t b1) {
    asm volatile(
        "mma.sync.aligned.m16n8k16.row.col.f32.f16.f16.f32 "
        "{%0,%1,%2,%3}, {%4,%5,%6,%7}, {%8,%9}, {%0,%1,%2,%3};"
        : "+f"(d[0]), "+f"(d[1]), "+f"(d[2]), "+f"(d[3])
        : "r"(a[0]), "r"(a[1]), "r"(a[2]), "r"(a[3]), "r"(b0), "r"(b1));
}

// ---------------------------------------------------------------------------
// Prepass: fp32 -> fp16 convert (8 elements per thread)
// ---------------------------------------------------------------------------
__global__ void f32_to_h8(__half* __restrict__ dst, const float* __restrict__ src, int n8)
{
    int i = blockIdx.x * blockDim.x + threadIdx.x;
    if (i >= n8) return;
    const float4* s = (const float4*)src + (size_t)i * 2;
    float4 a = s[0], b = s[1];
    uint4 o;
    o.x = h2u(__floats2half2_rn(a.x, a.y));
    o.y = h2u(__floats2half2_rn(a.z, a.w));
    o.z = h2u(__floats2half2_rn(b.x, b.y));
    o.w = h2u(__floats2half2_rn(b.z, b.w));
    ((uint4*)dst)[i] = o;
}

// ---------------------------------------------------------------------------
// RoPE: fp32 qkv -> half for q (scaled) and k.
// ---------------------------------------------------------------------------
__global__ void rope_h(const float* __restrict__ qkv, __half* __restrict__ qkv_h,
                       const int* __restrict__ positions, int S)
{
    int idx = blockIdx.x * blockDim.x + threadIdx.x;
    int total = S * (NQ + NKV) * (DH / 2);
    if (idx >= total) return;
    int hf = idx & 63;
    int h  = (idx >> 6) % (NQ + NKV);
    int s  = idx / ((NQ + NKV) * 64);

    const float* x = qkv + (size_t)s * QKV_COLS + h * DH;
    __half* y      = qkv_h + (size_t)s * QKV_COLS + h * DH;
    double inv  = exp(-log(10000.0) * (double)hf / 64.0);
    double phd  = (double)positions[s] * inv;
    const double TWO_PI = 6.283185307179586476925286766559;
    double red = phd - TWO_PI * rint(phd / TWO_PI);
    float c, sn;
    __sincosf((float)red, &sn, &c);
    float x1 = x[hf];
    float x2 = x[hf + 64];
    float r1 = x1 * c - x2 * sn;
    float r2 = x2 * c + x1 * sn;
    float scale = (h < NQ) ? ATT_SCALE : 1.0f;
    y[hf]      = __float2half_rn(r1 * scale);
    y[hf + 64] = __float2half_rn(r2 * scale);
}

// V region: fp32 -> half passthrough
__global__ void conv_v_h(const float* __restrict__ qkv, __half* __restrict__ qkv_h, int S)
{
    int i = blockIdx.x * blockDim.x + threadIdx.x;
    int total = S * NKV * DH;
    if (i >= total) return;
    int r = i / (NKV * DH);
    int c = i % (NKV * DH);
    size_t off = (size_t)r * QKV_COLS + (NQ + NKV) * DH + c;
    qkv_h[off] = __float2half_rn(qkv[off]);
}

// ---------------------------------------------------------------------------
// fp16 WMMA GEMM v3 (unchanged from R11): 128x128 CTA tile, BK=32, 4-stage,
// 8 warps, warp tile 32x64, 2 CTAs/SM.
// ---------------------------------------------------------------------------
#define BMh 128
#define BNh 128
#define BKh 32
#define NSTG 4
#define ALDh 40
#define BLDh 136
#define ASTGh (BMh * ALDh)
#define BSTGh (BKh * BLDh)
#define GEMMH_SMEM ((NSTG * (ASTGh + BSTGh)) * 2)   // 75776 bytes

__global__ __launch_bounds__(256, 2) void gemm_h16(
    const __half* __restrict__ A, const __half* __restrict__ B,
    float* __restrict__ C, int M, int N, int K)
{
    extern __shared__ __half smh[];
    __half* Asm = smh;
    __half* Bsm = smh + NSTG * ASTGh;

    const int tid = threadIdx.x;
    const int wid = tid >> 5;
    const int wr  = wid >> 1;
    const int wc  = wid & 1;

    const int brow = blockIdx.y * BMh;
    const int bcol = blockIdx.x * BNh;

    const int niter = K / BKh;

#define LOAD_STAGE(st, k0)                                                        \
    do {                                                                          \
        __half* as = Asm + (st) * ASTGh;                                          \
        __half* bs = Bsm + (st) * BSTGh;                                          \
        _Pragma("unroll")                                                         \
        for (int i = 0; i < 2; i++) {                                             \
            int idx = tid + i * 256;                                              \
            int r = idx >> 2; int c = (idx & 3) * 8;                              \
            cp_async16(as + r * ALDh + c,                                         \
                       A + (size_t)(brow + r) * K + (k0) + c);                    \
        }                                                                         \
        _Pragma("unroll")                                                         \
        for (int i = 0; i < 2; i++) {                                             \
            int idx = tid + i * 256;                                              \
            int r = idx >> 4; int c = (idx & 15) * 8;                             \
            cp_async16(bs + r * BLDh + c,                                         \
                       B + (size_t)((k0) + r) * N + bcol + c);                    \
        }                                                                         \
    } while (0)

    LOAD_STAGE(0, 0);
    asm volatile("cp.async.commit_group;\n");
    LOAD_STAGE(1, BKh);
    asm volatile("cp.async.commit_group;\n");
    LOAD_STAGE(2, 2 * BKh);
    asm volatile("cp.async.commit_group;\n");

    wmma::fragment<wmma::accumulator, 16, 16, 16, float> acc[2][4];
#pragma unroll
    for (int i = 0; i < 2; i++)
#pragma unroll
        for (int j = 0; j < 4; j++) wmma::fill_fragment(acc[i][j], 0.0f);

    for (int it = 0; it < niter; it++) {
        asm volatile("cp.async.wait_group 2;\n");
        __syncthreads();

        const int kn = (it + 3) * BKh;
        if (kn < K) LOAD_STAGE((it + 3) % NSTG, kn);
        asm volatile("cp.async.commit_group;\n");

        const int st = it % NSTG;
        const __half* as = Asm + st * ASTGh + (wr * 32) * ALDh;
        const __half* bs = Bsm + st * BSTGh + wc * 64;

#pragma unroll
        for (int kk = 0; kk < BKh; kk += 16) {
            wmma::fragment<wmma::matrix_a, 16, 16, 16, __half, wmma::row_major> af[2];
            wmma::fragment<wmma::matrix_b, 16, 16, 16, __half, wmma::row_major> bf[4];
#pragma unroll
            for (int i = 0; i < 2; i++)
                wmma::load_matrix_sync(af[i], as + (i * 16) * ALDh + kk, ALDh);
#pragma unroll
            for (int j = 0; j < 4; j++)
                wmma::load_matrix_sync(bf[j], bs + kk * BLDh + j * 16, BLDh);
#pragma unroll
            for (int i = 0; i < 2; i++)
#pragma unroll
                for (int j = 0; j < 4; j++)
                    wmma::mma_sync(acc[i][j], af[i], bf[j], acc[i][j]);
        }
    }

#pragma unroll
    for (int i = 0; i < 2; i++)
#pragma unroll
        for (int j = 0; j < 4; j++) {
            float* cp = C + (size_t)(brow + wr * 32 + i * 16) * N + bcol + wc * 64 + j * 16;
            wmma::store_matrix_sync(cp, acc[i][j], N, wmma::mem_row_major);
        }
#undef LOAD_STAGE
}

// ---------------------------------------------------------------------------
// FA2 causal attention: BQ=256 (16 warps, 512 threads), BKV=128 double-buffered.
// Grid: (S/256, NQ). Each warp owns 16 q-rows; register S/P/O.
// ---------------------------------------------------------------------------
#define KLD 136                  // halves per smem row (128 + 8 pad)
#define QROWS 256
#define QS_OFF   0
#define KS_OFF   (QROWS * KLD)             // 2 stages of [128][KLD]
#define VS_OFF   (KS_OFF + 2 * 128 * KLD)
#define FA2_SMEM ((VS_OFF + 2 * 128 * KLD) * 2)   // 208896 bytes

__global__ __launch_bounds__(512, 1) void attn_fa2(
    const __half* __restrict__ qkv_h, __half* __restrict__ out_h, int S)
{
    extern __shared__ char smc[];
    __half* Qs = (__half*)smc + QS_OFF;
    __half* Ks = (__half*)smc + KS_OFF;
    __half* Vs = (__half*)smc + VS_OFF;

    const int qblk = gridDim.x - 1 - blockIdx.x;   // long CTAs first
    const int h    = blockIdx.y;
    const int g    = h / GRP;
    const int tid  = threadIdx.x;
    const int wid  = tid >> 5;
    const int lane = tid & 31;

    const int r0  = wid * 16 + (lane >> 2);        // local q row of c0/c1 (0..255)
    const int q0  = qblk * QROWS + r0;             // global q row

    // ---- prologue: Q tile (256x128) + KV stage 0 via cp.async ----
#pragma unroll
    for (int i = 0; i < 8; i++) {
        int idx = tid + i * 512;
        int r = idx >> 4; int c = (idx & 15) * 8;
        cp_async16(Qs + r * KLD + c,
                   qkv_h + (size_t)(qblk * QROWS + r) * QKV_COLS + h * DH + c);
    }
#define LOAD_KV(st, kt)                                                            \
    do {                                                                           \
        __half* ks = Ks + (st) * 128 * KLD;                                        \
        __half* vs = Vs + (st) * 128 * KLD;                                        \
        _Pragma("unroll")                                                          \
        for (int i = 0; i < 4; i++) {                                              \
            int idx = tid + i * 512;                                               \
            int r = idx >> 4; int c = (idx & 15) * 8;                              \
            size_t base = (size_t)((kt) * 128 + r) * QKV_COLS + g * DH + c;        \
            cp_async16(ks + r * KLD + c, qkv_h + base + NQ*DH);                    \
            cp_async16(vs + r * KLD + c, qkv_h + base + (NQ+NKV)*DH);              \
        }                                                                          \
    } while (0)
    LOAD_KV(0, 0);
    asm volatile("cp.async.commit_group;\n");
    asm volatile("cp.async.wait_group 0;\n");
    __syncthreads();

    // ---- Q fragments: 8 k-tiles of m16k16 via ldmatrix.x4 ----
    uint32_t qa[8][4];
    {
        uint32_t base = s2u(Qs + (wid * 16 + (lane & 15)) * KLD + ((lane >> 4) * 8));
#pragma unroll
        for (int kd = 0; kd < 8; kd++)
            ldsm_x4(qa[kd], base + kd * 32);
    }

    float m0 = -1e30f, m1 = -1e30f, l0 = 0.f, l1 = 0.f;
    float of[16][4];
#pragma unroll
    for (int j = 0; j < 16; j++)
#pragma unroll
        for (int i = 0; i < 4; i++) of[j][i] = 0.f;

    const int nkt = 2 * qblk + 2;                  // 128-wide kv tiles
    for (int kt = 0; kt < nkt; kt++) {
        const int st = kt & 1;
        if (kt > 0) {
            asm volatile("cp.async.wait_group 0;\n");
            __syncthreads();
        }
        if (kt + 1 < nkt) LOAD_KV(st ^ 1, kt + 1);
        asm volatile("cp.async.commit_group;\n");

        const __half* K0 = Ks + st * 128 * KLD;
        const __half* V0 = Vs + st * 128 * KLD;

        // ---- S = Q @ K^T : 16 kv n-tiles x 8 d k-tiles ----
        float sc[16][4];
#pragma unroll
        for (int j = 0; j < 16; j++)
#pragma unroll
            for (int i = 0; i < 4; i++) sc[j][i] = 0.f;

        {
            uint32_t kbase = s2u(K0 + ((lane >> 4) * 8 + (lane & 7)) * KLD
                                    + (((lane >> 3) & 1) * 8));
#pragma unroll
            for (int jp = 0; jp < 8; jp++) {
#pragma unroll
                for (int kd = 0; kd < 8; kd++) {
                    uint32_t kb[4];
                    ldsm_x4(kb, kbase + jp * (16 * KLD * 2) + kd * 32);
                    mma16816(sc[2 * jp],     qa[kd], kb[0], kb[1]);
                    mma16816(sc[2 * jp + 1], qa[kd], kb[2], kb[3]);
                }
            }
        }

        // ---- causal mask (last two kv tiles): global key > global q row ----
        if (kt >= nkt - 2) {
            const int cb = 2 * (lane & 3);
            const int kbase_g = kt * 128;
#pragma unroll
            for (int j = 0; j < 16; j++) {
                int c0 = kbase_g + j * 8 + cb;
                int c1 = c0 + 1;
                if (c0 > q0)     sc[j][0] = -1e30f;
                if (c1 > q0)     sc[j][1] = -1e30f;
                if (c0 > q0 + 8) sc[j][2] = -1e30f;
                if (c1 > q0 + 8) sc[j][3] = -1e30f;
            }
        }

        // ---- online softmax in registers ----
        float tm0 = sc[0][0], tm1 = sc[0][2];
#pragma unroll
        for (int j = 0; j < 16; j++) {
            tm0 = fmaxf(tm0, fmaxf(sc[j][0], sc[j][1]));
            tm1 = fmaxf(tm1, fmaxf(sc[j][2], sc[j][3]));
        }
        tm0 = fmaxf(tm0, __shfl_xor_sync(0xffffffffu, tm0, 1));
        tm0 = fmaxf(tm0, __shfl_xor_sync(0xffffffffu, tm0, 2));
        tm1 = fmaxf(tm1, __shfl_xor_sync(0xffffffffu, tm1, 1));
        tm1 = fmaxf(tm1, __shfl_xor_sync(0xffffffffu, tm1, 2));

        float mn0 = fmaxf(m0, tm0), mn1 = fmaxf(m1, tm1);
        float corr0 = __expf(m0 - mn0), corr1 = __expf(m1 - mn1);
        m0 = mn0; m1 = mn1;

        float ps0 = 0.f, ps1 = 0.f;
#pragma unroll
        for (int j = 0; j < 16; j++) {
            sc[j][0] = __expf(sc[j][0] - mn0);
            sc[j][1] = __expf(sc[j][1] - mn0);
            sc[j][2] = __expf(sc[j][2] - mn1);
            sc[j][3] = __expf(sc[j][3] - mn1);
            ps0 += sc[j][0] + sc[j][1];
            ps1 += sc[j][2] + sc[j][3];
        }
        ps0 += __shfl_xor_sync(0xffffffffu, ps0, 1);
        ps0 += __shfl_xor_sync(0xffffffffu, ps0, 2);
        ps1 += __shfl_xor_sync(0xffffffffu, ps1, 1);
        ps1 += __shfl_xor_sync(0xffffffffu, ps1, 2);
        l0 = l0 * corr0 + ps0;
        l1 = l1 * corr1 + ps1;

#pragma unroll
        for (int j = 0; j < 16; j++) {
            of[j][0] *= corr0; of[j][1] *= corr0;
            of[j][2] *= corr1; of[j][3] *= corr1;
        }

        // ---- P a-frags from S accumulators (C->A layout identity) ----
        uint32_t pa[8][4];
#pragma unroll
        for (int k2 = 0; k2 < 8; k2++) {
            pa[k2][0] = h2u(__floats2half2_rn(sc[2 * k2][0],     sc[2 * k2][1]));
            pa[k2][1] = h2u(__floats2half2_rn(sc[2 * k2][2],     sc[2 * k2][3]));
            pa[k2][2] = h2u(__floats2half2_rn(sc[2 * k2 + 1][0], sc[2 * k2 + 1][1]));
            pa[k2][3] = h2u(__floats2half2_rn(sc[2 * k2 + 1][2], sc[2 * k2 + 1][3]));
        }

        // ---- O += P @ V : 8 d n-tile pairs x 8 kv k-tiles ----
        {
            uint32_t vbase = s2u(V0 + (((lane >> 3) & 1) * 8 + (lane & 7)) * KLD
                                    + ((lane >> 4) * 8));
#pragma unroll
            for (int jp = 0; jp < 8; jp++) {
#pragma unroll
                for (int k2 = 0; k2 < 8; k2++) {
                    uint32_t vb[4];
                    ldsm_x4_t(vb, vbase + k2 * (16 * KLD * 2) + jp * 32);
                    mma16816(of[2 * jp],     pa[k2], vb[0], vb[1]);
                    mma16816(of[2 * jp + 1], pa[k2], vb[2], vb[3]);
                }
            }
        }
    }

    // ---- epilogue: normalize and store half ----
    float il0 = 1.f / l0, il1 = 1.f / l1;
    __half* o0 = out_h + (size_t)q0 * (NQ * DH) + h * DH;
    __half* o1 = out_h + (size_t)(q0 + 8) * (NQ * DH) + h * DH;
    const int cb = 2 * (lane & 3);
#pragma unroll
    for (int jd = 0; jd < 16; jd++) {
        int col = jd * 8 + cb;
        *(__half2*)(o0 + col) = __floats2half2_rn(of[jd][0] * il0, of[jd][1] * il0);
        *(__half2*)(o1 + col) = __floats2half2_rn(of[jd][2] * il1, of[jd][3] * il1);
    }
#undef LOAD_KV
}

// ---------------------------------------------------------------------------
// Launch
// ---------------------------------------------------------------------------
extern "C" void kernel_launch(void* const* d_in, const int* in_sizes, int n_in,
                              void* d_out, int out_size)
{
    const int*   positions = (const int*)d_in[0];
    const float* hidden    = (const float*)d_in[1];
    const float* w_qkv     = (const float*)d_in[2];
    const float* w_o       = (const float*)d_in[3];
    float*       out       = (float*)d_out;

    const int S = in_sizes[0];

    float *qkv;
    __half *qkv_h, *attn_h, *hid_h, *wqkv_h, *wo_h;
    cudaGetSymbolAddress((void**)&qkv, g_qkv);
    cudaGetSymbolAddress((void**)&qkv_h, g_qkv_h);
    cudaGetSymbolAddress((void**)&attn_h, g_attn_h);
    cudaGetSymbolAddress((void**)&hid_h, g_hid_h);
    cudaGetSymbolAddress((void**)&wqkv_h, g_wqkv_h);
    cudaGetSymbolAddress((void**)&wo_h, g_wo_h);

    // 0) fp32 -> fp16 prepass
    {
        int n8 = (S * HID) / 8;
        f32_to_h8<<<(n8 + 255) / 256, 256>>>(hid_h, hidden, n8);
        n8 = (HID * QKV_COLS) / 8;
        f32_to_h8<<<(n8 + 255) / 256, 256>>>(wqkv_h, w_qkv, n8);
        n8 = (NQ * DH * HID) / 8;
        f32_to_h8<<<(n8 + 255) / 256, 256>>>(wo_h, w_o, n8);
    }

    // 1) qkv = hidden @ w_qkv
    cudaFuncSetAttribute(gemm_h16, cudaFuncAttributeMaxDynamicSharedMemorySize, GEMMH_SMEM);
    gemm_h16<<<dim3(QKV_COLS/BNh, S/BMh), 256, GEMMH_SMEM>>>(hid_h, wqkv_h, qkv, S, QKV_COLS, HID);

    // 2) RoPE -> half q(scaled)/k ; convert v -> half
    {
        int total = S * (NQ + NKV) * (DH / 2);
        rope_h<<<(total + 255) / 256, 256>>>(qkv, qkv_h, positions, S);
        total = S * NKV * DH;
        conv_v_h<<<(total + 255) / 256, 256>>>(qkv, qkv_h, S);
    }

    // 3) FA2 causal attention (BQ=256, BKV=128, 512 threads)
    cudaFuncSetAttribute(attn_fa2, cudaFuncAttributeMaxDynamicSharedMemorySize, FA2_SMEM);
    attn_fa2<<<dim3(S/QROWS, NQ), 512, FA2_SMEM>>>(qkv_h, attn_h, S);

    // 4) out = attn @ w_o
    gemm_h16<<<dim3(HID/BNh, S/BMh), 256, GEMMH_SMEM>>>(attn_h, wo_h, out, S, HID, NQ*DH);
}

// round 16
// speedup vs baseline: 1.1235x; 1.1235x over previous
#include <cuda_runtime.h>
#include <cuda_fp16.h>
#include <mma.h>
#include <math.h>
#include <stdint.h>

using namespace nvcuda;

// Problem constants
#define SEQ    4096
#define HID    4096
#define NQ     32
#define NKV    8
#define DH     128
#define GRP    4
#define QKV_COLS (NQ*DH + 2*NKV*DH)   // 6144
#define ATT_SCALE 0.08838834764831845f
#define LOG2E 1.4426950408889634f

// Scratch (no cudaMalloc allowed)
__device__ float  g_qkv[(size_t)SEQ * QKV_COLS];      // fp32 qkv (GEMM1 out)
__device__ __half g_qkv_h[(size_t)SEQ * QKV_COLS];    // half q(rope,scaled),k(rope),v
__device__ __half g_attn_h[(size_t)SEQ * (NQ*DH)];    // half attention output
__device__ __half g_hid_h[(size_t)SEQ * HID];
__device__ __half g_wqkv_h[(size_t)HID * QKV_COLS];
__device__ __half g_wo_h[(size_t)(NQ*DH) * HID];

__device__ __forceinline__ void cp_async16(void* smem_dst, const void* gmem_src)
{
    unsigned dst = (unsigned)__cvta_generic_to_shared(smem_dst);
    asm volatile("cp.async.cg.shared.global [%0], [%1], 16;\n" :: "r"(dst), "l"(gmem_src));
}
__device__ __forceinline__ uint32_t h2u(__half2 h) { return *(uint32_t*)&h; }
__device__ __forceinline__ uint32_t s2u(const void* p) {
    return (uint32_t)__cvta_generic_to_shared(p);
}

__device__ __forceinline__ void ldsm_x4(uint32_t* r, uint32_t addr) {
    asm volatile("ldmatrix.sync.aligned.m8n8.x4.shared.b16 {%0,%1,%2,%3}, [%4];"
        : "=r"(r[0]), "=r"(r[1]), "=r"(r[2]), "=r"(r[3]) : "r"(addr));
}
__device__ __forceinline__ void ldsm_x4_t(uint32_t* r, uint32_t addr) {
    asm volatile("ldmatrix.sync.aligned.m8n8.x4.trans.shared.b16 {%0,%1,%2,%3}, [%4];"
        : "=r"(r[0]), "=r"(r[1]), "=r"(r[2]), "=r"(r[3]) : "r"(addr));
}
__device__ __forceinline__ void mma16816(float* d, const uint32_t* a, uint32_t b0, uint32_t b1) {
    asm volatile(
        "mma.sync.aligned.m16n8k16.row.col.f32.f16.f16.f32 "
        "{%0,%1,%2,%3}, {%4,%5,%6,%7}, {%8,%9}, {%0,%1,%2,%3};"
        : "+f"(d[0]), "+f"(d[1]), "+f"(d[2]), "+f"(d[3])
        : "r"(a[0]), "r"(a[1]), "r"(a[2]), "r"(a[3]), "r"(b0), "r"(b1));
}

// ---------------------------------------------------------------------------
// Prepass: fp32 -> fp16 convert (8 elements per thread)
// ---------------------------------------------------------------------------
__global__ void f32_to_h8(__half* __restrict__ dst, const float* __restrict__ src, int n8)
{
    int i = blockIdx.x * blockDim.x + threadIdx.x;
    if (i >= n8) return;
    const float4* s = (const float4*)src + (size_t)i * 2;
    float4 a = s[0], b = s[1];
    uint4 o;
    o.x = h2u(__floats2half2_rn(a.x, a.y));
    o.y = h2u(__floats2half2_rn(a.z, a.w));
    o.z = h2u(__floats2half2_rn(b.x, b.y));
    o.w = h2u(__floats2half2_rn(b.z, b.w));
    ((uint4*)dst)[i] = o;
}

// ---------------------------------------------------------------------------
// RoPE: fp32 qkv -> half for q (scaled) and k.
// ---------------------------------------------------------------------------
__global__ void rope_h(const float* __restrict__ qkv, __half* __restrict__ qkv_h,
                       const int* __restrict__ positions, int S)
{
    int idx = blockIdx.x * blockDim.x + threadIdx.x;
    int total = S * (NQ + NKV) * (DH / 2);
    if (idx >= total) return;
    int hf = idx & 63;
    int h  = (idx >> 6) % (NQ + NKV);
    int s  = idx / ((NQ + NKV) * 64);

    const float* x = qkv + (size_t)s * QKV_COLS + h * DH;
    __half* y      = qkv_h + (size_t)s * QKV_COLS + h * DH;
    double inv  = exp(-log(10000.0) * (double)hf / 64.0);
    double phd  = (double)positions[s] * inv;
    const double TWO_PI = 6.283185307179586476925286766559;
    double red = phd - TWO_PI * rint(phd / TWO_PI);
    float c, sn;
    __sincosf((float)red, &sn, &c);
    float x1 = x[hf];
    float x2 = x[hf + 64];
    float r1 = x1 * c - x2 * sn;
    float r2 = x2 * c + x1 * sn;
    float scale = (h < NQ) ? ATT_SCALE : 1.0f;
    y[hf]      = __float2half_rn(r1 * scale);
    y[hf + 64] = __float2half_rn(r2 * scale);
}

// V region: fp32 -> half passthrough
__global__ void conv_v_h(const float* __restrict__ qkv, __half* __restrict__ qkv_h, int S)
{
    int i = blockIdx.x * blockDim.x + threadIdx.x;
    int total = S * NKV * DH;
    if (i >= total) return;
    int r = i / (NKV * DH);
    int c = i % (NKV * DH);
    size_t off = (size_t)r * QKV_COLS + (NQ + NKV) * DH + c;
    qkv_h[off] = __float2half_rn(qkv[off]);
}

// ---------------------------------------------------------------------------
// fp16 WMMA GEMM: 128x128 CTA tile, BK=32, 5-stage cp.async, 8 warps,
// warp tile 32x64, 2 CTAs/SM.
// ---------------------------------------------------------------------------
#define BMh 128
#define BNh 128
#define BKh 32
#define NSTG 5
#define ALDh 40
#define BLDh 136
#define ASTGh (BMh * ALDh)
#define BSTGh (BKh * BLDh)
#define GEMMH_SMEM ((NSTG * (ASTGh + BSTGh)) * 2)   // 94720 bytes

__global__ __launch_bounds__(256, 2) void gemm_h16(
    const __half* __restrict__ A, const __half* __restrict__ B,
    float* __restrict__ C, int M, int N, int K)
{
    extern __shared__ __half smh[];
    __half* Asm = smh;
    __half* Bsm = smh + NSTG * ASTGh;

    const int tid = threadIdx.x;
    const int wid = tid >> 5;
    const int wr  = wid >> 1;
    const int wc  = wid & 1;

    const int brow = blockIdx.y * BMh;
    const int bcol = blockIdx.x * BNh;

    const int niter = K / BKh;

#define LOAD_STAGE(st, k0)                                                        \
    do {                                                                          \
        __half* as = Asm + (st) * ASTGh;                                          \
        __half* bs = Bsm + (st) * BSTGh;                                          \
        _Pragma("unroll")                                                         \
        for (int i = 0; i < 2; i++) {                                             \
            int idx = tid + i * 256;                                              \
            int r = idx >> 2; int c = (idx & 3) * 8;                              \
            cp_async16(as + r * ALDh + c,                                         \
                       A + (size_t)(brow + r) * K + (k0) + c);                    \
        }                                                                         \
        _Pragma("unroll")                                                         \
        for (int i = 0; i < 2; i++) {                                             \
            int idx = tid + i * 256;                                              \
            int r = idx >> 4; int c = (idx & 15) * 8;                             \
            cp_async16(bs + r * BLDh + c,                                         \
                       B + (size_t)((k0) + r) * N + bcol + c);                    \
        }                                                                         \
    } while (0)

    LOAD_STAGE(0, 0);
    asm volatile("cp.async.commit_group;\n");
    LOAD_STAGE(1, BKh);
    asm volatile("cp.async.commit_group;\n");
    LOAD_STAGE(2, 2 * BKh);
    asm volatile("cp.async.commit_group;\n");
    LOAD_STAGE(3, 3 * BKh);
    asm volatile("cp.async.commit_group;\n");

    wmma::fragment<wmma::accumulator, 16, 16, 16, float> acc[2][4];
#pragma unroll
    for (int i = 0; i < 2; i++)
#pragma unroll
        for (int j = 0; j < 4; j++) wmma::fill_fragment(acc[i][j], 0.0f);

    for (int it = 0; it < niter; it++) {
        asm volatile("cp.async.wait_group 3;\n");
        __syncthreads();

        const int kn = (it + 4) * BKh;
        if (kn < K) LOAD_STAGE((it + 4) % NSTG, kn);
        asm volatile("cp.async.commit_group;\n");

        const int st = it % NSTG;
        const __half* as = Asm + st * ASTGh + (wr * 32) * ALDh;
        const __half* bs = Bsm + st * BSTGh + wc * 64;

#pragma unroll
        for (int kk = 0; kk < BKh; kk += 16) {
            wmma::fragment<wmma::matrix_a, 16, 16, 16, __half, wmma::row_major> af[2];
            wmma::fragment<wmma::matrix_b, 16, 16, 16, __half, wmma::row_major> bf[4];
#pragma unroll
            for (int i = 0; i < 2; i++)
                wmma::load_matrix_sync(af[i], as + (i * 16) * ALDh + kk, ALDh);
#pragma unroll
            for (int j = 0; j < 4; j++)
                wmma::load_matrix_sync(bf[j], bs + kk * BLDh + j * 16, BLDh);
#pragma unroll
            for (int i = 0; i < 2; i++)
#pragma unroll
                for (int j = 0; j < 4; j++)
                    wmma::mma_sync(acc[i][j], af[i], bf[j], acc[i][j]);
        }
    }

#pragma unroll
    for (int i = 0; i < 2; i++)
#pragma unroll
        for (int j = 0; j < 4; j++) {
            float* cp = C + (size_t)(brow + wr * 32 + i * 16) * N + bcol + wc * 64 + j * 16;
            wmma::store_matrix_sync(cp, acc[i][j], N, wmma::mem_row_major);
        }
#undef LOAD_STAGE
}

// ---------------------------------------------------------------------------
// FA2 causal attention: BQ=128, BKV=128, raw mma.sync, register S/P/O.
// Grid: (S/128, NQ). Block: 256 threads (8 warps, 16 q-rows each).
// Softmax exp via ex2.approx.f16x2 (h2exp2) -> output is the half P frag.
// ---------------------------------------------------------------------------
#define KLD 136                  // halves per smem row (128 + 8 pad)
#define QS_OFF   0
#define KS_OFF   (128 * KLD)               // 2 stages of [128][KLD]
#define VS_OFF   (KS_OFF + 2 * 128 * KLD)
#define FA2_SMEM ((VS_OFF + 2 * 128 * KLD) * 2)

__global__ __launch_bounds__(256, 1) void attn_fa2(
    const __half* __restrict__ qkv_h, __half* __restrict__ out_h, int S)
{
    extern __shared__ char smc[];
    __half* Qs = (__half*)smc + QS_OFF;
    __half* Ks = (__half*)smc + KS_OFF;
    __half* Vs = (__half*)smc + VS_OFF;

    const int qblk = gridDim.x - 1 - blockIdx.x;   // long CTAs first
    const int h    = blockIdx.y;
    const int g    = h / GRP;
    const int tid  = threadIdx.x;
    const int wid  = tid >> 5;
    const int lane = tid & 31;

    const int r0  = wid * 16 + (lane >> 2);        // local q row of c0/c1
    const int q0  = qblk * 128 + r0;

    // ---- prologue: Q tile (128x128) + KV stage 0 via cp.async ----
#pragma unroll
    for (int i = 0; i < 8; i++) {
        int idx = tid + i * 256;
        int r = idx >> 4; int c = (idx & 15) * 8;
        cp_async16(Qs + r * KLD + c,
                   qkv_h + (size_t)(qblk * 128 + r) * QKV_COLS + h * DH + c);
    }
#define LOAD_KV(st, kt)                                                            \
    do {                                                                           \
        __half* ks = Ks + (st) * 128 * KLD;                                        \
        __half* vs = Vs + (st) * 128 * KLD;                                        \
        _Pragma("unroll")                                                          \
        for (int i = 0; i < 8; i++) {                                              \
            int idx = tid + i * 256;                                               \
            int r = idx >> 4; int c = (idx & 15) * 8;                              \
            size_t base = (size_t)((kt) * 128 + r) * QKV_COLS + g * DH + c;        \
            cp_async16(ks + r * KLD + c, qkv_h + base + NQ*DH);                    \
            cp_async16(vs + r * KLD + c, qkv_h + base + (NQ+NKV)*DH);              \
        }                                                                          \
    } while (0)
    LOAD_KV(0, 0);
    asm volatile("cp.async.commit_group;\n");
    asm volatile("cp.async.wait_group 0;\n");
    __syncthreads();

    // ---- Q fragments: 8 k-tiles of m16k16 via ldmatrix.x4 ----
    uint32_t qa[8][4];
    {
        uint32_t base = s2u(Qs + (wid * 16 + (lane & 15)) * KLD + ((lane >> 4) * 8));
#pragma unroll
        for (int kd = 0; kd < 8; kd++)
            ldsm_x4(qa[kd], base + kd * 32);
    }

    float m0 = -1e30f, m1 = -1e30f, l0 = 0.f, l1 = 0.f;
    float of[16][4];
#pragma unroll
    for (int j = 0; j < 16; j++)
#pragma unroll
        for (int i = 0; i < 4; i++) of[j][i] = 0.f;

    const int nkt = qblk + 1;
    for (int kt = 0; kt < nkt; kt++) {
        const int st = kt & 1;
        if (kt > 0) {
            asm volatile("cp.async.wait_group 0;\n");
            __syncthreads();
        }
        if (kt + 1 < nkt) LOAD_KV(st ^ 1, kt + 1);
        asm volatile("cp.async.commit_group;\n");

        const __half* K0 = Ks + st * 128 * KLD;
        const __half* V0 = Vs + st * 128 * KLD;

        // ---- S = Q @ K^T : 16 kv n-tiles x 8 d k-tiles ----
        float sc[16][4];
#pragma unroll
        for (int j = 0; j < 16; j++)
#pragma unroll
            for (int i = 0; i < 4; i++) sc[j][i] = 0.f;

        {
            uint32_t kbase = s2u(K0 + ((lane >> 4) * 8 + (lane & 7)) * KLD
                                    + (((lane >> 3) & 1) * 8));
#pragma unroll
            for (int jp = 0; jp < 8; jp++) {
#pragma unroll
                for (int kd = 0; kd < 8; kd++) {
                    uint32_t kb[4];
                    ldsm_x4(kb, kbase + jp * (16 * KLD * 2) + kd * 32);
                    mma16816(sc[2 * jp],     qa[kd], kb[0], kb[1]);
                    mma16816(sc[2 * jp + 1], qa[kd], kb[2], kb[3]);
                }
            }
        }

        // ---- causal mask (diagonal tile only): local col > local row ----
        if (kt == qblk) {
            const int cb = 2 * (lane & 3);
            const int lr0 = r0, lr1 = r0 + 8;
#pragma unroll
            for (int j = 0; j < 16; j++) {
                int c0 = j * 8 + cb;
                int c1 = c0 + 1;
                if (c0 > lr0) sc[j][0] = -1e30f;
                if (c1 > lr0) sc[j][1] = -1e30f;
                if (c0 > lr1) sc[j][2] = -1e30f;
                if (c1 > lr1) sc[j][3] = -1e30f;
            }
        }

        // ---- online softmax: max in fp32, exp via h2exp2 (half2 MUFU) ----
        float tm0 = sc[0][0], tm1 = sc[0][2];
#pragma unroll
        for (int j = 0; j < 16; j++) {
            tm0 = fmaxf(tm0, fmaxf(sc[j][0], sc[j][1]));
            tm1 = fmaxf(tm1, fmaxf(sc[j][2], sc[j][3]));
        }
        tm0 = fmaxf(tm0, __shfl_xor_sync(0xffffffffu, tm0, 1));
        tm0 = fmaxf(tm0, __shfl_xor_sync(0xffffffffu, tm0, 2));
        tm1 = fmaxf(tm1, __shfl_xor_sync(0xffffffffu, tm1, 1));
        tm1 = fmaxf(tm1, __shfl_xor_sync(0xffffffffu, tm1, 2));

        float mn0 = fmaxf(m0, tm0), mn1 = fmaxf(m1, tm1);
        float corr0 = __expf(m0 - mn0), corr1 = __expf(m1 - mn1);
        m0 = mn0; m1 = mn1;
        const float mb0 = mn0 * LOG2E, mb1 = mn1 * LOG2E;

        // P fragments directly from h2exp2 output (C->A layout identity)
        uint32_t pa[8][4];
        float ps0 = 0.f, ps1 = 0.f;
#pragma unroll
        for (int k2 = 0; k2 < 8; k2++) {
#pragma unroll
            for (int half_i = 0; half_i < 2; half_i++) {
                const int j = 2 * k2 + half_i;
                __half2 a0 = __floats2half2_rn(fmaf(sc[j][0], LOG2E, -mb0),
                                               fmaf(sc[j][1], LOG2E, -mb0));
                __half2 a1 = __floats2half2_rn(fmaf(sc[j][2], LOG2E, -mb1),
                                               fmaf(sc[j][3], LOG2E, -mb1));
                __half2 e0 = h2exp2(a0);
                __half2 e1 = h2exp2(a1);
                pa[k2][2 * half_i + 0] = h2u(e0);
                pa[k2][2 * half_i + 1] = h2u(e1);
                float2 f0 = __half22float2(e0);
                float2 f1 = __half22float2(e1);
                ps0 += f0.x + f0.y;
                ps1 += f1.x + f1.y;
            }
        }
        ps0 += __shfl_xor_sync(0xffffffffu, ps0, 1);
        ps0 += __shfl_xor_sync(0xffffffffu, ps0, 2);
        ps1 += __shfl_xor_sync(0xffffffffu, ps1, 1);
        ps1 += __shfl_xor_sync(0xffffffffu, ps1, 2);
        l0 = l0 * corr0 + ps0;
        l1 = l1 * corr1 + ps1;

#pragma unroll
        for (int j = 0; j < 16; j++) {
            of[j][0] *= corr0; of[j][1] *= corr0;
            of[j][2] *= corr1; of[j][3] *= corr1;
        }

        // ---- O += P @ V : 8 d n-tile pairs x 8 kv k-tiles ----
        {
            uint32_t vbase = s2u(V0 + (((lane >> 3) & 1) * 8 + (lane & 7)) * KLD
                                    + ((lane >> 4) * 8));
#pragma unroll
            for (int jp = 0; jp < 8; jp++) {
#pragma unroll
                for (int k2 = 0; k2 < 8; k2++) {
                    uint32_t vb[4];
                    ldsm_x4_t(vb, vbase + k2 * (16 * KLD * 2) + jp * 32);
                    mma16816(of[2 * jp],     pa[k2], vb[0], vb[1]);
                    mma16816(of[2 * jp + 1], pa[k2], vb[2], vb[3]);
                }
            }
        }
    }

    // ---- epilogue: normalize and store half ----
    float il0 = 1.f / l0, il1 = 1.f / l1;
    __half* o0 = out_h + (size_t)q0 * (NQ * DH) + h * DH;
    __half* o1 = out_h + (size_t)(q0 + 8) * (NQ * DH) + h * DH;
    const int cb = 2 * (lane & 3);
#pragma unroll
    for (int jd = 0; jd < 16; jd++) {
        int col = jd * 8 + cb;
        *(__half2*)(o0 + col) = __floats2half2_rn(of[jd][0] * il0, of[jd][1] * il0);
        *(__half2*)(o1 + col) = __floats2half2_rn(of[jd][2] * il1, of[jd][3] * il1);
    }
#undef LOAD_KV
}

// ---------------------------------------------------------------------------
// Launch
// ---------------------------------------------------------------------------
extern "C" void kernel_launch(void* const* d_in, const int* in_sizes, int n_in,
                              void* d_out, int out_size)
{
    const int*   positions = (const int*)d_in[0];
    const float* hidden    = (const float*)d_in[1];
    const float* w_qkv     = (const float*)d_in[2];
    const float* w_o       = (const float*)d_in[3];
    float*       out       = (float*)d_out;

    const int S = in_sizes[0];

    float *qkv;
    __half *qkv_h, *attn_h, *hid_h, *wqkv_h, *wo_h;
    cudaGetSymbolAddress((void**)&qkv, g_qkv);
    cudaGetSymbolAddress((void**)&qkv_h, g_qkv_h);
    cudaGetSymbolAddress((void**)&attn_h, g_attn_h);
    cudaGetSymbolAddress((void**)&hid_h, g_hid_h);
    cudaGetSymbolAddress((void**)&wqkv_h, g_wqkv_h);
    cudaGetSymbolAddress((void**)&wo_h, g_wo_h);

    // 0) fp32 -> fp16 prepass
    {
        int n8 = (S * HID) / 8;
        f32_to_h8<<<(n8 + 255) / 256, 256>>>(hid_h, hidden, n8);
        n8 = (HID * QKV_COLS) / 8;
        f32_to_h8<<<(n8 + 255) / 256, 256>>>(wqkv_h, w_qkv, n8);
        n8 = (NQ * DH * HID) / 8;
        f32_to_h8<<<(n8 + 255) / 256, 256>>>(wo_h, w_o, n8);
    }

    // 1) qkv = hidden @ w_qkv
    cudaFuncSetAttribute(gemm_h16, cudaFuncAttributeMaxDynamicSharedMemorySize, GEMMH_SMEM);
    gemm_h16<<<dim3(QKV_COLS/BNh, S/BMh), 256, GEMMH_SMEM>>>(hid_h, wqkv_h, qkv, S, QKV_COLS, HID);

    // 2) RoPE -> half q(scaled)/k ; convert v -> half
    {
        int total = S * (NQ + NKV) * (DH / 2);
        rope_h<<<(total + 255) / 256, 256>>>(qkv, qkv_h, positions, S);
        total = S * NKV * DH;
        conv_v_h<<<(total + 255) / 256, 256>>>(qkv, qkv_h, S);
    }

    // 3) FA2 causal attention (BQ=128, BKV=128, 256 threads)
    cudaFuncSetAttribute(attn_fa2, cudaFuncAttributeMaxDynamicSharedMemorySize, FA2_SMEM);
    attn_fa2<<<dim3(S/128, NQ), 256, FA2_SMEM>>>(qkv_h, attn_h, S);

    // 4) out = attn @ w_o
    gemm_h16<<<dim3(HID/BNh, S/BMh), 256, GEMMH_SMEM>>>(attn_h, wo_h, out, S, HID, NQ*DH);
}